// round 4
// baseline (speedup 1.0000x reference)
#include <cuda_runtime.h>
#include <cuda_fp16.h>
#include <math.h>

#define SQ   4096
#define DD   512
#define VV   32000
#define HH   50
#define GHX  150
#define GHXP 160
#define EMBD 10
#define XIN  (DD + VV)

#define NBE  128   // encoder blocks
#define NPB  4     // neurons per block
#define RPB  12    // gate rows per block per matrix

#define NBD  128   // decoder blocks
#define VPB  250   // vocab cols per block
#define VPBP 256   // padded

// ---------------- device scratch ----------------
__device__ __align__(16) float g_h0[2][DD];
__device__ __align__(16) float g_h1[2][DD];
__device__ float g_dense_gi[GHX];
__device__ float g_ugfb[GHX];
__device__ float g_Zacc;
__device__ float g_rZ;
__device__ float g_h2vec[HH];

struct __align__(128) PadCtr { unsigned int v; unsigned int pad[31]; };
__device__ PadCtr g_cntE, g_flagE, g_cntD, g_flagD;

__device__ __forceinline__ float sigm(float x) { return 1.f / (1.f + __expf(-x)); }

__device__ __forceinline__ void p_arrive(unsigned int* c) {
    asm volatile("red.release.gpu.add.u32 [%0], %1;" :: "l"(c), "r"(1u) : "memory");
}
__device__ __forceinline__ void p_wait_ge(unsigned int* p, unsigned int tgt) {
    unsigned int v;
    do { asm volatile("ld.acquire.gpu.u32 %0, [%1];" : "=r"(v) : "l"(p) : "memory"); }
    while (v < tgt);
}
__device__ __forceinline__ void p_publish(unsigned int* p, unsigned int val) {
    asm volatile("st.release.gpu.u32 [%0], %1;" :: "l"(p), "r"(val) : "memory");
}

// flag-split grid barrier: arrivals on one line, release flag on another.
__device__ __forceinline__ void bar_flag(unsigned int* cnt, unsigned int* flag,
                                         unsigned int epoch, unsigned int nb) {
    __syncthreads();
    if (threadIdx.x == 0) {
        p_arrive(cnt);
        if (blockIdx.x == 0) { p_wait_ge(cnt, epoch * nb); p_publish(flag, epoch); }
        else                 { p_wait_ge(flag, epoch); }
    }
    __syncthreads();
}

// 8-half dot with fp32 accumulation
__device__ __forceinline__ float dot8h(uint4 a, uint4 b) {
    const __half2* pa = (const __half2*)&a;
    const __half2* pb = (const __half2*)&b;
    float acc = 0.f;
    #pragma unroll
    for (int i = 0; i < 4; i++) {
        float2 x = __half22float2(pa[i]);
        float2 y = __half22float2(pb[i]);
        acc += x.x * y.x + x.y * y.y;
    }
    return acc;
}

// ---------------- init ----------------
__global__ void k_init() {
    int t = blockIdx.x * blockDim.x + threadIdx.x;
    if (t == 0) {
        g_cntE.v = 0u; g_flagE.v = 0u; g_cntD.v = 0u; g_flagD.v = 0u;
        g_Zacc = 1.f; g_rZ = 1.f;
    }
    if (t < DD) { g_h0[0][t] = 0.f; g_h0[1][t] = 0.f; g_h1[0][t] = 0.f; g_h1[1][t] = 0.f; }
    if (t < GHX) g_ugfb[t] = 0.f;
}

// ---------------- encoder ----------------
__global__ void __launch_bounds__(256, 1) k_encoder(
    const int*   __restrict__ input_mol, const float* __restrict__ emb,
    const float* __restrict__ eWih0, const float* __restrict__ eWhh0,
    const float* __restrict__ ebih0, const float* __restrict__ ebhh0,
    const float* __restrict__ eWih1, const float* __restrict__ eWhh1,
    const float* __restrict__ ebih1, const float* __restrict__ ebhh1)
{
    extern __shared__ float sm[];
    float* sWhh0 = sm;                      // [12][512]
    float* sWih1 = sWhh0 + RPB * DD;        // [12][512]
    float* sWhh1 = sWih1 + RPB * DD;        // [12][512]
    float* sWih0 = sWhh1 + RPB * DD;        // [12][16]
    float* sb    = sWih0 + RPB * 16;        // 48
    float* h0s   = sb + 48;                 // [512]
    float* h1s   = h0s + DD;                // [512]
    float* dots  = h1s + DD;                // [36]
    float* xs    = dots + 36;               // [16]

    const int b = blockIdx.x, tid = threadIdx.x;

    for (int lr = 0; lr < RPB; lr++) {
        int gr = (lr >> 2) * DD + b * NPB + (lr & 3);
        for (int c = tid; c < DD; c += 256) {
            sWhh0[lr * DD + c] = eWhh0[gr * DD + c];
            sWih1[lr * DD + c] = eWih1[gr * DD + c];
            sWhh1[lr * DD + c] = eWhh1[gr * DD + c];
        }
        if (tid < EMBD) sWih0[lr * 16 + tid] = eWih0[gr * EMBD + tid];
        if (tid == 0) {
            sb[lr]      = ebih0[gr];
            sb[12 + lr] = ebhh0[gr];
            sb[24 + lr] = ebih1[gr];
            sb[36 + lr] = ebhh1[gr];
        }
    }
    if (tid < EMBD) xs[tid] = emb[input_mol[0] * EMBD + tid];
    __syncthreads();

    unsigned int epoch = 0;

    // prologue: h0_0
    if (tid < NPB) {
        int q = tid;
        float gir = sb[q], giz = sb[4 + q], gin = sb[8 + q];
        #pragma unroll
        for (int c = 0; c < EMBD; c++) {
            float xv = xs[c];
            gir += sWih0[q * 16 + c] * xv;
            giz += sWih0[(4 + q) * 16 + c] * xv;
            gin += sWih0[(8 + q) * 16 + c] * xv;
        }
        float r = sigm(gir + sb[12 + q]);
        float z = sigm(giz + sb[16 + q]);
        float n = tanhf(gin + r * sb[20 + q]);
        g_h0[0][b * NPB + q] = (1.f - z) * n;
    }
    bar_flag(&g_cntE.v, &g_flagE.v, ++epoch, NBE);

    for (int k = 0; k < SQ; k++) {
        const int cur = k & 1, nxt = cur ^ 1;
        if (tid < 128)      ((float4*)h0s)[tid]       = ((const float4*)g_h0[cur])[tid];
        else                ((float4*)h1s)[tid - 128] = ((const float4*)g_h1[nxt])[tid - 128];
        if (k + 1 < SQ && tid < EMBD) xs[tid] = emb[input_mol[k + 1] * EMBD + tid];
        __syncthreads();

        const int w = tid >> 5, lane = tid & 31;
        for (int tau = w; tau < 36; tau += 8) {
            int m = tau / 12, lr = tau % 12;
            const float* wr = (m == 0 ? sWhh0 : (m == 1 ? sWih1 : sWhh1)) + lr * DD;
            const float* v  = (m == 2) ? h1s : h0s;
            const float4* w4 = (const float4*)wr;
            const float4* v4 = (const float4*)v;
            float acc = 0.f;
            #pragma unroll
            for (int i = 0; i < 4; i++) {
                float4 a = w4[i * 32 + lane];
                float4 x = v4[i * 32 + lane];
                acc += a.x * x.x + a.y * x.y + a.z * x.z + a.w * x.w;
            }
            #pragma unroll
            for (int o = 16; o; o >>= 1) acc += __shfl_xor_sync(0xffffffffu, acc, o);
            if (lane == 0) dots[tau] = acc;
        }
        __syncthreads();

        if (tid < NPB) {
            int q = tid, n_idx = b * NPB + q;
            {   // layer1: h1_k
                float r = sigm(dots[12 + q]     + sb[24 + q] + dots[24 + q]     + sb[36 + q]);
                float z = sigm(dots[12 + 4 + q] + sb[28 + q] + dots[24 + 4 + q] + sb[40 + q]);
                float n = tanhf(dots[12 + 8 + q] + sb[32 + q] + r * (dots[24 + 8 + q] + sb[44 + q]));
                g_h1[cur][n_idx] = (1.f - z) * n + z * h1s[n_idx];
            }
            if (k + 1 < SQ) {   // layer0: h0_{k+1}
                float gir = sb[q], giz = sb[4 + q], gin = sb[8 + q];
                #pragma unroll
                for (int c = 0; c < EMBD; c++) {
                    float xv = xs[c];
                    gir += sWih0[q * 16 + c] * xv;
                    giz += sWih0[(4 + q) * 16 + c] * xv;
                    gin += sWih0[(8 + q) * 16 + c] * xv;
                }
                float r = sigm(gir + dots[q]     + sb[12 + q]);
                float z = sigm(giz + dots[4 + q] + sb[16 + q]);
                float n = tanhf(gin + r * (dots[8 + q] + sb[20 + q]));
                g_h0[nxt][n_idx] = (1.f - z) * n + z * h0s[n_idx];
            }
        }
        bar_flag(&g_cntE.v, &g_flagE.v, ++epoch, NBE);
    }
}

// ---------------- mid ----------------
__global__ void k_mid(const float* __restrict__ dWih1, const float* __restrict__ dbih1) {
    const float* dense = g_h1[(SQ - 1) & 1];
    int g = threadIdx.x;
    if (g < GHX) {
        float acc = dbih1[g];
        const float* row = dWih1 + (size_t)g * XIN;
        for (int c = 0; c < DD; c++) acc += row[c] * dense[c];
        g_dense_gi[g] = acc;
    }
}

// ---------------- decoder: 1 counter-round per step ----------------
__global__ void __launch_bounds__(256, 1) k_decoder(
    const float* __restrict__ dWih1,
    const float* __restrict__ dWhh1, const float* __restrict__ dWih2,
    const float* __restrict__ dWhh2,
    const float* __restrict__ dbhh1, const float* __restrict__ dbih2,
    const float* __restrict__ dbhh2,
    const float* __restrict__ W2, const float* __restrict__ b2,
    float* __restrict__ out)
{
    extern __shared__ float smf[];
    __half* WfbH = (__half*)smf;                    // [150][256] halves
    __half* W2tH = WfbH + GHX * VPBP;               // [50][256] halves
    float*  tW1  = (float*)(W2tH + HH * VPBP);      // [50][160] Whh1^T
    float*  tW2i = tW1  + HH * GHXP;                // [50][160] Wih2^T
    float*  tW2h = tW2i + HH * GHXP;                // [50][160] Whh2^T
    __half* esh  = (__half*)(tW2h + HH * GHXP);     // [256] halves (16B aligned)
    float*  fp   = (float*)(esh + VPBP);
    float*  h2s  = fp;            fp += 64;
    float*  h1s  = fp;            fp += 64;
    float*  h2os = fp;            fp += 64;
    float*  gia  = fp;            fp += GHX;
    float*  gha  = fp;            fp += GHX;
    float*  sgi  = fp;            fp += GHX;
    float*  sb1  = fp;            fp += GHX;
    float*  sb2i = fp;            fp += GHX;
    float*  sb2h = fp;            fp += GHX;
    float*  rzbuf = fp;           fp += 4;
    float*  zred  = fp;           fp += 8;

    const int b = blockIdx.x, tid = threadIdx.x;
    const int j0 = b * VPB;
    const int w = tid >> 5, lane = tid & 31;

    for (int idx = tid; idx < GHX * VPBP; idx += 256) {
        int r = idx / VPBP, c = idx % VPBP;
        WfbH[idx] = __float2half((c < VPB) ? dWih1[(size_t)r * XIN + DD + j0 + c] : 0.f);
    }
    for (int idx = tid; idx < HH * VPBP; idx += 256) {
        int c = idx / VPBP, j = idx % VPBP;
        W2tH[idx] = __float2half((j < VPB) ? W2[(size_t)(j0 + j) * HH + c] : 0.f);
    }
    if (b == 0) {
        for (int idx = tid; idx < HH * GHX; idx += 256) {
            int g = idx / HH, c = idx % HH;
            tW1 [c * GHXP + g] = dWhh1[idx];
            tW2i[c * GHXP + g] = dWih2[idx];
            tW2h[c * GHXP + g] = dWhh2[idx];
        }
        if (tid < GHX) { sb1[tid] = dbhh1[tid]; sb2i[tid] = dbih2[tid]; sb2h[tid] = dbhh2[tid];
                         sgi[tid] = g_dense_gi[tid]; }
        if (tid < HH)  { h1s[tid] = 0.f; h2os[tid] = 0.f; }
    }
    const float b2r = (tid < VPB) ? b2[j0 + tid] : 0.f;
    __syncthreads();

    float eprev = 0.f;

    for (int t = 0; t < SQ; t++) {
        if (b == 0) {
            // ---- serial phase B (this block is the coordinator) ----
            if (tid == 0) {
                if (t > 0) p_wait_ge(&g_cntD.v, (unsigned)(NBD * t));
                float rz = 1.f / g_Zacc;
                rzbuf[0] = rz; g_rZ = rz; g_Zacc = 0.f;
            }
            __syncthreads();
            const float rz = rzbuf[0];
            if (tid < GHX) {
                float gi = sgi[tid] + g_ugfb[tid] * rz;  g_ugfb[tid] = 0.f;
                float gh = sb1[tid];
                #pragma unroll
                for (int c = 0; c < HH; c++) gh += tW1[c * GHXP + tid] * h1s[c];
                gia[tid] = gi; gha[tid] = gh;
            }
            __syncthreads();
            if (tid < HH) {
                float r = sigm(gia[tid] + gha[tid]);
                float z = sigm(gia[HH + tid] + gha[HH + tid]);
                float n = tanhf(gia[2 * HH + tid] + r * gha[2 * HH + tid]);
                h1s[tid] = (1.f - z) * n + z * h1s[tid];
            }
            __syncthreads();
            if (tid < GHX) {
                float gi = sb2i[tid], gh = sb2h[tid];
                #pragma unroll
                for (int c = 0; c < HH; c++) {
                    gi += tW2i[c * GHXP + tid] * h1s[c];
                    gh += tW2h[c * GHXP + tid] * h2os[c];
                }
                gia[tid] = gi; gha[tid] = gh;
            }
            __syncthreads();
            if (tid < HH) {
                float r = sigm(gia[tid] + gha[tid]);
                float z = sigm(gia[HH + tid] + gha[HH + tid]);
                float n = tanhf(gia[2 * HH + tid] + r * gha[2 * HH + tid]);
                float h2n = (1.f - z) * n + z * h2os[tid];
                h2os[tid] = h2n; h2s[tid] = h2n;
                g_h2vec[tid] = h2n;
            }
            __syncthreads();
            if (tid == 0) p_publish(&g_flagD.v, (unsigned)(t + 1));
        } else {
            if (tid == 0) p_wait_ge(&g_flagD.v, (unsigned)(t + 1));
            __syncthreads();
            if (tid < HH) h2s[tid] = g_h2vec[tid];
            if (tid == 0) rzbuf[0] = g_rZ;
            __syncthreads();
        }

        // ---- parallel phase (all blocks) ----
        if (t > 0 && tid < VPB)
            __stcs(&out[(size_t)(t - 1) * VV + j0 + tid], eprev * rzbuf[0]);

        float e = 0.f;
        if (tid < VPB) {
            float acc = b2r;
            #pragma unroll
            for (int c = 0; c < HH; c++) acc += h2s[c] * __half2float(W2tH[c * VPBP + tid]);
            e = __expf(acc);
        }
        eprev = e;
        esh[tid] = __float2half(e);

        float zs = e;
        #pragma unroll
        for (int o = 16; o; o >>= 1) zs += __shfl_xor_sync(0xffffffffu, zs, o);
        if (lane == 0) zred[w] = zs;
        __syncthreads();                         // esh + zred ready
        if (tid == 0) {
            float z8 = zred[0] + zred[1] + zred[2] + zred[3]
                     + zred[4] + zred[5] + zred[6] + zred[7];
            atomicAdd(&g_Zacc, z8);
        }

        // feedback matvec: es held in registers, weights streamed from smem
        const uint4 ev = ((const uint4*)esh)[lane];   // 8 halves of e per lane
        for (int r = w; r < GHX; r += 8) {
            uint4 wv = ((const uint4*)(WfbH + r * VPBP))[lane];
            float acc = dot8h(wv, ev);
            #pragma unroll
            for (int o = 16; o; o >>= 1) acc += __shfl_xor_sync(0xffffffffu, acc, o);
            if (lane == 0) atomicAdd(&g_ugfb[r], acc);
        }
        __syncthreads();
        if (tid == 0) p_arrive(&g_cntD.v);
    }

    // epilogue: final row normalization after all blocks' last Z arrives
    if (tid == 0) { p_wait_ge(&g_cntD.v, (unsigned)(NBD * SQ)); rzbuf[0] = 1.f / g_Zacc; }
    __syncthreads();
    if (tid < VPB)
        __stcs(&out[(size_t)(SQ - 1) * VV + j0 + tid], eprev * rzbuf[0]);
}

// ---------------- launcher ----------------
extern "C" void kernel_launch(void* const* d_in, const int* in_sizes, int n_in,
                              void* d_out, int out_size) {
    const int*   input_mol = (const int*)  d_in[0];
    const float* emb   = (const float*)d_in[1];
    const float* eWih0 = (const float*)d_in[2];
    const float* eWhh0 = (const float*)d_in[3];
    const float* ebih0 = (const float*)d_in[4];
    const float* ebhh0 = (const float*)d_in[5];
    const float* eWih1 = (const float*)d_in[6];
    const float* eWhh1 = (const float*)d_in[7];
    const float* ebih1 = (const float*)d_in[8];
    const float* ebhh1 = (const float*)d_in[9];
    const float* dWih1 = (const float*)d_in[10];
    const float* dWhh1 = (const float*)d_in[11];
    // d_in[12] = dbih1 (folded into k_mid)
    const float* dbih1 = (const float*)d_in[12];
    const float* dbhh1 = (const float*)d_in[13];
    const float* dWih2 = (const float*)d_in[14];
    const float* dWhh2 = (const float*)d_in[15];
    const float* dbih2 = (const float*)d_in[16];
    const float* dbhh2 = (const float*)d_in[17];
    const float* W2    = (const float*)d_in[18];
    const float* b2    = (const float*)d_in[19];
    float* out = (float*)d_out;

    const size_t esmem = (size_t)(3 * RPB * DD + RPB * 16 + 48 + 2 * DD + 36 + 16) * sizeof(float);
    const size_t dsmem = (size_t)(GHX * VPBP + HH * VPBP) * sizeof(__half)
                       + (size_t)(3 * HH * GHXP) * sizeof(float)
                       + (size_t)VPBP * sizeof(__half)
                       + (size_t)(3 * 64 + 6 * GHX + 4 + 8) * sizeof(float);

    cudaFuncSetAttribute(k_encoder, cudaFuncAttributeMaxDynamicSharedMemorySize, (int)esmem);
    cudaFuncSetAttribute(k_decoder, cudaFuncAttributeMaxDynamicSharedMemorySize, (int)dsmem);

    k_init<<<3, 256>>>();
    k_encoder<<<NBE, 256, esmem>>>(input_mol, emb, eWih0, eWhh0, ebih0, ebhh0,
                                   eWih1, eWhh1, ebih1, ebhh1);
    k_mid<<<1, 256>>>(dWih1, dbih1);
    k_decoder<<<NBD, 256, dsmem>>>(dWih1, dWhh1, dWih2, dWhh2,
                                   dbhh1, dbih2, dbhh2, W2, b2, out);
}

// round 5
// speedup vs baseline: 2.2014x; 2.2014x over previous
#include <cuda_runtime.h>
#include <cuda_fp16.h>
#include <math.h>

#define SQ   4096
#define DD   512
#define VV   32000
#define HH   50
#define GHX  150
#define GHXP 160
#define EMBD 10
#define XIN  (DD + VV)

#define NBE  128
#define NPB  4
#define RPB  12

#define NBD  128
#define VPB  250
#define VPBP 256
#define WFBP 264   // padded Wfb row (halves)

// ---------------- device scratch ----------------
__device__ __align__(16) float g_h0[2][DD];
__device__ __align__(16) float g_h1[2][DD];
__device__ float g_dense_gi[GHX];
// per-step accumulators: one 128B line per row; row 150 = Z
__device__ float g_acc[(size_t)(SQ + 1) * 151 * 32];

struct __align__(128) PadCtr { unsigned int v; unsigned int pad[31]; };
__device__ PadCtr g_cntE8[8];
__device__ PadCtr g_cntD8[8];

__device__ __forceinline__ float sigm(float x) { return 1.f / (1.f + __expf(-x)); }

__device__ __forceinline__ void p_arrive(unsigned int* c) {
    asm volatile("red.release.gpu.add.u32 [%0], %1;" :: "l"(c), "r"(1u) : "memory");
}
__device__ __forceinline__ void p_wait_ge(unsigned int* p, unsigned int tgt) {
    unsigned int v;
    do { asm volatile("ld.acquire.gpu.u32 %0, [%1];" : "=r"(v) : "l"(p) : "memory"); }
    while (v < tgt);
}

// leaderless tree barrier: arrive on line (bid&7), poll all 8 lines. 1 hop.
__device__ __forceinline__ void bar_tree(PadCtr* lines, unsigned int epoch) {
    __syncthreads();
    if (threadIdx.x == 0) p_arrive(&lines[blockIdx.x & 7].v);
    if (threadIdx.x < 8)  p_wait_ge(&lines[threadIdx.x].v, 16u * epoch);
    __syncthreads();
}

__device__ __forceinline__ float dot8h(uint4 a, uint4 b) {
    const __half2* pa = (const __half2*)&a;
    const __half2* pb = (const __half2*)&b;
    float acc = 0.f;
    #pragma unroll
    for (int i = 0; i < 4; i++) {
        float2 x = __half22float2(pa[i]);
        float2 y = __half22float2(pb[i]);
        acc += x.x * y.x + x.y * y.y;
    }
    return acc;
}

// ---------------- init (resets ALL persistent state each graph replay) ----
__global__ void k_init() {
    int t = blockIdx.x * blockDim.x + threadIdx.x;
    if (t < 8) { g_cntE8[t].v = 0u; g_cntD8[t].v = 0u; }
    if (t < DD) { g_h0[0][t] = 0.f; g_h0[1][t] = 0.f; g_h1[0][t] = 0.f; g_h1[1][t] = 0.f; }
    if (t < (SQ + 1) * 151)
        g_acc[(size_t)t * 32] = (t == 150) ? 1.f : 0.f;   // step0: ugfb=0, Z=1
}

// ---------------- encoder: persistent, tree barrier per step ----------------
__global__ void __launch_bounds__(256, 1) k_encoder(
    const int*   __restrict__ input_mol, const float* __restrict__ emb,
    const float* __restrict__ eWih0, const float* __restrict__ eWhh0,
    const float* __restrict__ ebih0, const float* __restrict__ ebhh0,
    const float* __restrict__ eWih1, const float* __restrict__ eWhh1,
    const float* __restrict__ ebih1, const float* __restrict__ ebhh1)
{
    extern __shared__ float sm[];
    float* sWhh0 = sm;
    float* sWih1 = sWhh0 + RPB * DD;
    float* sWhh1 = sWih1 + RPB * DD;
    float* sWih0 = sWhh1 + RPB * DD;     // [12][16]
    float* sb    = sWih0 + RPB * 16;     // 48
    float* h0s   = sb + 48;              // [512]
    float* h1s   = h0s + DD;             // [512]
    float* dots  = h1s + DD;             // [36]
    float* xs    = dots + 36;            // [16]

    const int b = blockIdx.x, tid = threadIdx.x;

    for (int lr = 0; lr < RPB; lr++) {
        int gr = (lr >> 2) * DD + b * NPB + (lr & 3);
        for (int c = tid; c < DD; c += 256) {
            sWhh0[lr * DD + c] = eWhh0[gr * DD + c];
            sWih1[lr * DD + c] = eWih1[gr * DD + c];
            sWhh1[lr * DD + c] = eWhh1[gr * DD + c];
        }
        if (tid < EMBD) sWih0[lr * 16 + tid] = eWih0[gr * EMBD + tid];
        if (tid == 0) {
            sb[lr]      = ebih0[gr];
            sb[12 + lr] = ebhh0[gr];
            sb[24 + lr] = ebih1[gr];
            sb[36 + lr] = ebhh1[gr];
        }
    }
    if (tid < EMBD) xs[tid] = emb[input_mol[0] * EMBD + tid];
    __syncthreads();

    unsigned int epoch = 0;

    if (tid < NPB) {   // prologue h0_0
        int q = tid;
        float gir = sb[q], giz = sb[4 + q], gin = sb[8 + q];
        #pragma unroll
        for (int c = 0; c < EMBD; c++) {
            float xv = xs[c];
            gir += sWih0[q * 16 + c] * xv;
            giz += sWih0[(4 + q) * 16 + c] * xv;
            gin += sWih0[(8 + q) * 16 + c] * xv;
        }
        float r = sigm(gir + sb[12 + q]);
        float z = sigm(giz + sb[16 + q]);
        float n = tanhf(gin + r * sb[20 + q]);
        __stcg(&g_h0[0][b * NPB + q], (1.f - z) * n);
    }
    bar_tree(g_cntE8, ++epoch);

    for (int k = 0; k < SQ; k++) {
        const int cur = k & 1, nxt = cur ^ 1;
        if (tid < 128)
            ((float4*)h0s)[tid] = __ldcg(((const float4*)g_h0[cur]) + tid);
        else
            ((float4*)h1s)[tid - 128] = __ldcg(((const float4*)g_h1[nxt]) + (tid - 128));
        if (k + 1 < SQ && tid < EMBD) xs[tid] = emb[input_mol[k + 1] * EMBD + tid];
        __syncthreads();

        const int w = tid >> 5, lane = tid & 31;
        for (int tau = w; tau < 36; tau += 8) {
            int m = tau / 12, lr = tau % 12;
            const float* wr = (m == 0 ? sWhh0 : (m == 1 ? sWih1 : sWhh1)) + lr * DD;
            const float* v  = (m == 2) ? h1s : h0s;
            const float4* w4 = (const float4*)wr;
            const float4* v4 = (const float4*)v;
            float acc = 0.f;
            #pragma unroll
            for (int i = 0; i < 4; i++) {
                float4 a = w4[i * 32 + lane];
                float4 x = v4[i * 32 + lane];
                acc += a.x * x.x + a.y * x.y + a.z * x.z + a.w * x.w;
            }
            #pragma unroll
            for (int o = 16; o; o >>= 1) acc += __shfl_xor_sync(0xffffffffu, acc, o);
            if (lane == 0) dots[tau] = acc;
        }
        __syncthreads();

        if (tid < NPB) {
            int q = tid, n_idx = b * NPB + q;
            {   // layer1: h1_k
                float r = sigm(dots[12 + q]     + sb[24 + q] + dots[24 + q]     + sb[36 + q]);
                float z = sigm(dots[12 + 4 + q] + sb[28 + q] + dots[24 + 4 + q] + sb[40 + q]);
                float n = tanhf(dots[12 + 8 + q] + sb[32 + q] + r * (dots[24 + 8 + q] + sb[44 + q]));
                __stcg(&g_h1[cur][n_idx], (1.f - z) * n + z * h1s[n_idx]);
            }
            if (k + 1 < SQ) {   // layer0: h0_{k+1}
                float gir = sb[q], giz = sb[4 + q], gin = sb[8 + q];
                #pragma unroll
                for (int c = 0; c < EMBD; c++) {
                    float xv = xs[c];
                    gir += sWih0[q * 16 + c] * xv;
                    giz += sWih0[(4 + q) * 16 + c] * xv;
                    gin += sWih0[(8 + q) * 16 + c] * xv;
                }
                float r = sigm(gir + dots[q]     + sb[12 + q]);
                float z = sigm(giz + dots[4 + q] + sb[16 + q]);
                float n = tanhf(gin + r * (dots[8 + q] + sb[20 + q]));
                __stcg(&g_h0[nxt][n_idx], (1.f - z) * n + z * h0s[n_idx]);
            }
        }
        bar_tree(g_cntE8, ++epoch);
    }
}

// ---------------- mid: dense part of decoder layer-1 input gates ----------------
__global__ void k_mid(const float* __restrict__ dWih1, const float* __restrict__ dbih1) {
    const float* dense = g_h1[(SQ - 1) & 1];
    int w = threadIdx.x >> 5, lane = threadIdx.x & 31;
    for (int g = w; g < GHX; g += 16) {
        const float* row = dWih1 + (size_t)g * XIN;
        float acc = 0.f;
        for (int c = lane; c < DD; c += 32) acc += row[c] * dense[c];
        #pragma unroll
        for (int o = 16; o; o >>= 1) acc += __shfl_xor_sync(0xffffffffu, acc, o);
        if (lane == 0) g_dense_gi[g] = dbih1[g] + acc;
    }
}

// ---------------- decoder: redundant phase B, 1 hop/step, 512 threads --------
__global__ void __launch_bounds__(512, 1) k_decoder(
    const float* __restrict__ dWih1,
    const float* __restrict__ dWhh1, const float* __restrict__ dWih2,
    const float* __restrict__ dWhh2,
    const float* __restrict__ dbhh1, const float* __restrict__ dbih2,
    const float* __restrict__ dbhh2,
    const float* __restrict__ W2, const float* __restrict__ b2,
    float* __restrict__ out)
{
    extern __shared__ unsigned char smraw[];
    __half* WfbH = (__half*)smraw;                 // [150][264]
    __half* W2tH = WfbH + GHX * WFBP;              // [50][256]
    __half* esh  = W2tH + HH * VPBP;               // [256]
    float*  fp   = (float*)(esh + VPBP);
    float*  tW1  = fp;  fp += HH * GHXP;           // Whh1^T [50][160]
    float*  tW2i = fp;  fp += HH * GHXP;
    float*  tW2h = fp;  fp += HH * GHXP;
    float*  sgi  = fp;  fp += GHX;
    float*  sb1  = fp;  fp += GHX;
    float*  sb2i = fp;  fp += GHX;
    float*  sb2h = fp;  fp += GHX;
    float*  gia  = fp;  fp += GHX;
    float*  gha  = fp;  fp += GHX;
    float*  h1s  = fp;  fp += 64;
    float*  h2os = fp;  fp += 64;
    float*  rzs  = fp;  fp += 4;
    float*  zred = fp;  fp += 16;

    const int b = blockIdx.x, tid = threadIdx.x;
    const int j0 = b * VPB;
    const int w = tid >> 5, lane = tid & 31;
    const int jcol = tid >> 1, hpar = tid & 1;
    const int sub = lane >> 3, kk = lane & 7;

    for (int idx = tid; idx < GHX * WFBP; idx += 512) {
        int r = idx / WFBP, c = idx % WFBP;
        WfbH[idx] = __float2half((c < VPB) ? dWih1[(size_t)r * XIN + DD + j0 + c] : 0.f);
    }
    for (int idx = tid; idx < HH * VPBP; idx += 512) {
        int c = idx >> 8, j = idx & 255;
        W2tH[idx] = __float2half((j < VPB) ? W2[(size_t)(j0 + j) * HH + c] : 0.f);
    }
    for (int idx = tid; idx < HH * GHX; idx += 512) {
        int g = idx / HH, c = idx % HH;
        tW1 [c * GHXP + g] = dWhh1[idx];
        tW2i[c * GHXP + g] = dWih2[idx];
        tW2h[c * GHXP + g] = dWhh2[idx];
    }
    if (tid < GHX) {
        sgi[tid] = g_dense_gi[tid];
        sb1[tid] = dbhh1[tid]; sb2i[tid] = dbih2[tid]; sb2h[tid] = dbhh2[tid];
    }
    if (tid < 64) { h1s[tid] = 0.f; h2os[tid] = 0.f; }
    if (tid >= 250 && tid < 256) esh[tid] = __float2half(0.f);
    const float b2r = (!hpar && jcol < VPB) ? b2[j0 + jcol] : 0.f;
    __syncthreads();

    float eprev = 0.f;

    for (int t = 0; t < SQ; t++) {
        // ---- single hop: wait for step t-1 contributions ----
        if (t > 0 && tid < 8) p_wait_ge(&g_cntD8[tid].v, 16u * (unsigned)t);
        __syncthreads();
        const float* accR = g_acc + (size_t)t * 151 * 32;
        if (tid == 0)  rzs[0] = 1.f / __ldcg(accR + 150 * 32);
        if (tid < GHX) gha[tid] = __ldcg(accR + tid * 32);   // raw ugfb
        __syncthreads();
        const float rz = rzs[0];

        // normalize & store previous step's outputs (Z(t-1) just arrived)
        if (t > 0 && !hpar && jcol < VPB)
            __stcs(&out[(size_t)(t - 1) * VV + j0 + jcol], eprev * rz);

        // ---- phase B (redundant, identical in every CTA) ----
        if (tid < GHX) {
            float gi = sgi[tid] + gha[tid] * rz;
            float gh = sb1[tid];
            #pragma unroll
            for (int c = 0; c < HH; c++) gh += tW1[c * GHXP + tid] * h1s[c];
            gia[tid] = gi; gha[tid] = gh;
        }
        __syncthreads();
        if (tid < HH) {
            float r = sigm(gia[tid] + gha[tid]);
            float z = sigm(gia[HH + tid] + gha[HH + tid]);
            float n = tanhf(gia[2 * HH + tid] + r * gha[2 * HH + tid]);
            h1s[tid] = (1.f - z) * n + z * h1s[tid];
        }
        __syncthreads();
        if (tid < GHX) {                       // gi2 rows (threads 0-149)
            float gi = sb2i[tid];
            #pragma unroll
            for (int c = 0; c < HH; c++) gi += tW2i[c * GHXP + tid] * h1s[c];
            gia[tid] = gi;
        } else if (tid >= 256 && tid < 256 + GHX) {   // gh2 rows (threads 256-405)
            int r2 = tid - 256;
            float gh = sb2h[r2];
            #pragma unroll
            for (int c = 0; c < HH; c++) gh += tW2h[c * GHXP + r2] * h2os[c];
            gha[r2] = gh;
        }
        __syncthreads();
        if (tid < HH) {
            float r = sigm(gia[tid] + gha[tid]);
            float z = sigm(gia[HH + tid] + gha[HH + tid]);
            float n = tanhf(gia[2 * HH + tid] + r * gha[2 * HH + tid]);
            h2os[tid] = (1.f - z) * n + z * h2os[tid];
        }
        __syncthreads();

        // ---- logits + exp (pair-split: 2 threads per vocab col) ----
        float acc = b2r;
        {
            const int c0 = hpar * 25;
            #pragma unroll
            for (int c = 0; c < 25; c++)
                acc += h2os[c0 + c] * __half2float(W2tH[(c0 + c) * VPBP + jcol]);
        }
        acc += __shfl_xor_sync(0xffffffffu, acc, 1);
        float e = __expf(acc);
        if (!hpar && jcol < VPB) esh[jcol] = __float2half(e);

        // Z partial: only even threads with valid col contribute
        float ze = (!hpar && jcol < VPB) ? e : 0.f;
        #pragma unroll
        for (int o = 16; o; o >>= 1) ze += __shfl_xor_sync(0xffffffffu, ze, o);
        if (lane == 0) zred[w] = ze;
        __syncthreads();                       // esh + zred ready

        float* accW = g_acc + (size_t)(t + 1) * 151 * 32;
        if (tid == 0) {
            float z = 0.f;
            #pragma unroll
            for (int i = 0; i < 16; i++) z += zred[i];
            atomicAdd(accW + 150 * 32, z);
        }

        // ---- fb matvec: 4 rows/warp, 8-lane groups, 3 passes ----
        const uint4* es4 = (const uint4*)esh;
        uint4 ev0 = es4[kk], ev1 = es4[kk + 8], ev2 = es4[kk + 16], ev3 = es4[kk + 24];
        #pragma unroll
        for (int p = 0; p < 3; p++) {
            int row = p * 64 + w * 4 + sub;
            int rowc = (row < GHX) ? row : (GHX - 1);
            const uint4* wr = (const uint4*)(WfbH + rowc * WFBP);
            float a = dot8h(wr[kk], ev0) + dot8h(wr[kk + 8], ev1)
                    + dot8h(wr[kk + 16], ev2) + dot8h(wr[kk + 24], ev3);
            a += __shfl_xor_sync(0xffffffffu, a, 1);
            a += __shfl_xor_sync(0xffffffffu, a, 2);
            a += __shfl_xor_sync(0xffffffffu, a, 4);
            if (kk == 0 && row < GHX) atomicAdd(accW + row * 32, a);
        }
        __syncthreads();
        if (tid == 0) p_arrive(&g_cntD8[b & 7].v);
        eprev = e;
    }

    // epilogue: final row
    if (tid < 8) p_wait_ge(&g_cntD8[tid].v, 16u * (unsigned)SQ);
    __syncthreads();
    if (tid == 0) rzs[0] = 1.f / __ldcg(g_acc + (size_t)SQ * 151 * 32 + 150 * 32);
    __syncthreads();
    if (!hpar && jcol < VPB)
        __stcs(&out[(size_t)(SQ - 1) * VV + j0 + jcol], eprev * rzs[0]);
}

// ---------------- launcher ----------------
extern "C" void kernel_launch(void* const* d_in, const int* in_sizes, int n_in,
                              void* d_out, int out_size) {
    const int*   input_mol = (const int*)  d_in[0];
    const float* emb   = (const float*)d_in[1];
    const float* eWih0 = (const float*)d_in[2];
    const float* eWhh0 = (const float*)d_in[3];
    const float* ebih0 = (const float*)d_in[4];
    const float* ebhh0 = (const float*)d_in[5];
    const float* eWih1 = (const float*)d_in[6];
    const float* eWhh1 = (const float*)d_in[7];
    const float* ebih1 = (const float*)d_in[8];
    const float* ebhh1 = (const float*)d_in[9];
    const float* dWih1 = (const float*)d_in[10];
    const float* dWhh1 = (const float*)d_in[11];
    const float* dbih1 = (const float*)d_in[12];
    const float* dbhh1 = (const float*)d_in[13];
    const float* dWih2 = (const float*)d_in[14];
    const float* dWhh2 = (const float*)d_in[15];
    const float* dbih2 = (const float*)d_in[16];
    const float* dbhh2 = (const float*)d_in[17];
    const float* W2    = (const float*)d_in[18];
    const float* b2    = (const float*)d_in[19];
    float* out = (float*)d_out;

    const size_t esmem = (size_t)(3 * RPB * DD + RPB * 16 + 48 + 2 * DD + 36 + 16) * sizeof(float);
    const size_t dsmem = (size_t)(GHX * WFBP + HH * VPBP + VPBP) * sizeof(__half)
                       + (size_t)(3 * HH * GHXP + 4 * GHX + 2 * GHX + 2 * 64 + 4 + 16) * sizeof(float);

    cudaFuncSetAttribute(k_encoder, cudaFuncAttributeMaxDynamicSharedMemorySize, (int)esmem);
    cudaFuncSetAttribute(k_decoder, cudaFuncAttributeMaxDynamicSharedMemorySize, (int)dsmem);

    k_init<<<((SQ + 1) * 151 + 255) / 256, 256>>>();
    k_encoder<<<NBE, 256, esmem>>>(input_mol, emb, eWih0, eWhh0, ebih0, ebhh0,
                                   eWih1, eWhh1, ebih1, ebhh1);
    k_mid<<<1, 512>>>(dWih1, dbih1);
    k_decoder<<<NBD, 512, dsmem>>>(dWih1, dWhh1, dWih2, dWhh2,
                                   dbhh1, dbih2, dbhh2, W2, b2, out);
}

// round 6
// speedup vs baseline: 2.2816x; 1.0364x over previous
#include <cuda_runtime.h>
#include <cuda_fp16.h>
#include <math.h>

#define SQ   4096
#define DD   512
#define VV   32000
#define HH   50
#define GHX  150
#define GHXP 160
#define EMBD 10
#define XIN  (DD + VV)

#define NBD  128
#define VPB  250
#define VPBP 256
#define WFBP 264
#define NFB  151      // 150 fb rows + Z row

// ---------------- device scratch ----------------
__device__ float g_h0seq[(size_t)SQ * DD];        // 8 MB
__device__ float g_gi1seq[(size_t)SQ * 3 * DD];   // 24 MB
__device__ __align__(16) float g_h1x[2][DD];
__device__ float g_dense_gi[GHX];
__device__ float g_acc[(size_t)(SQ + 1) * NFB * 32];

struct __align__(128) PadCtr { unsigned int v; unsigned int pad[31]; };
__device__ PadCtr g_cnt0, g_cnt1, g_cntD8[8];

__device__ __forceinline__ float sigm(float x) { return 1.f / (1.f + __expf(-x)); }

__device__ __forceinline__ void p_arrive(unsigned int* c) {
    asm volatile("red.release.gpu.add.u32 [%0], %1;" :: "l"(c), "r"(1u) : "memory");
}
__device__ __forceinline__ void p_wait_ge(unsigned int* p, unsigned int tgt) {
    unsigned int v;
    do { asm volatile("ld.acquire.gpu.u32 %0, [%1];" : "=r"(v) : "l"(p) : "memory"); }
    while ((int)(v - tgt) < 0);
}
#define CLUSTER_SYNC() do { \
    asm volatile("barrier.cluster.arrive.aligned;" ::: "memory"); \
    asm volatile("barrier.cluster.wait.aligned;" ::: "memory"); } while (0)

__device__ __forceinline__ float dot8h(uint4 a, uint4 b) {
    const __half2* pa = (const __half2*)&a;
    const __half2* pb = (const __half2*)&b;
    float acc = 0.f;
    #pragma unroll
    for (int i = 0; i < 4; i++) {
        float2 x = __half22float2(pa[i]);
        float2 y = __half22float2(pb[i]);
        acc += x.x * y.x + x.y * y.y;
    }
    return acc;
}

// 512-col half matvec, 2 threads/row (p = column half). Weights chunked:
// halves of cols [cb*8, cb*8+8) of row r live at ((cb*192 + r)*8 ...).
// HFMA2 accumulation, float flush every 4 chunks (32 cols).
__device__ __forceinline__ float mvrow_h(const uint4* w4r, const uint4* h4, int p) {
    float acc = 0.f;
    #pragma unroll
    for (int o = 0; o < 8; o++) {
        __half2 ha = __floats2half2_rn(0.f, 0.f);
        #pragma unroll
        for (int i = 0; i < 4; i++) {
            int cb = (p << 5) + (o << 2) + i;
            uint4 wv = w4r[cb * 192];
            uint4 hv = h4[cb];
            const __half2* wp = (const __half2*)&wv;
            const __half2* hp = (const __half2*)&hv;
            ha = __hfma2(wp[0], hp[0], ha);
            ha = __hfma2(wp[1], hp[1], ha);
            ha = __hfma2(wp[2], hp[2], ha);
            ha = __hfma2(wp[3], hp[3], ha);
        }
        float2 f = __half22float2(ha);
        acc += f.x + f.y;
    }
    return acc;
}

// ---------------- init ----------------
__global__ void k_init() {
    int t = blockIdx.x * blockDim.x + threadIdx.x;
    if (t == 0) { g_cnt0.v = 0u; g_cnt1.v = 0u; }
    if (t < 8)  g_cntD8[t].v = 0u;
    if (t < (SQ + 1) * NFB)
        g_acc[(size_t)t * 32] = (t == GHX) ? 1.f : 0.f;   // step0: ugfb=0, Z=1
}

// ---------------- encoder: 3 pipelined clusters of 8 CTAs ----------------
__global__ void __launch_bounds__(416, 1) __cluster_dims__(8, 1, 1)
k_encoder(
    const int*   __restrict__ input_mol, const float* __restrict__ emb,
    const float* __restrict__ eWih0, const float* __restrict__ eWhh0,
    const float* __restrict__ ebih0, const float* __restrict__ ebhh0,
    const float* __restrict__ eWih1, const float* __restrict__ eWhh1,
    const float* __restrict__ ebih1, const float* __restrict__ ebhh1)
{
    extern __shared__ unsigned char smraw[];
    __half*  WtH  = (__half*)smraw;                       // 192*512 chunked
    float*   fp   = (float*)(smraw + 192 * 512 * 2);
    float*   hA   = fp;  fp += DD;                        // state (fp32)
    float*   dots = fp;  fp += 192;                       // gh per row
    float*   g192 = fp;  fp += 192;                       // gi (stage0) / gi1 (stage2)
    float*   wih0 = fp;  fp += 192 * EMBD;                // stage0 only
    float*   bA   = fp;  fp += 192;                       // gi bias
    float*   bB   = fp;  fp += 192;                       // gh bias
    float*   xs   = fp;  fp += 16;
    __half2* hh2  = (__half2*)fp;                         // 256 half2 = state fp16

    const int tid  = threadIdx.x;
    const int role = blockIdx.x >> 3;
    const int ci   = blockIdx.x & 7;
    const int bd   = blockDim.x;
    const uint4* h4 = (const uint4*)hh2;

    // ---- weight load ----
    const float* Wsrc = (role == 0) ? eWhh0 : (role == 1) ? eWih1 : eWhh1;
    for (int idx = tid; idx < 192 * 512; idx += bd) {
        int r = idx >> 9, c = idx & 511;
        int grow = (role == 1) ? (ci * 192 + r) : ((r >> 6) * DD + ci * 64 + (r & 63));
        WtH[((c >> 3) * 192 + r) * 8 + (c & 7)] = __float2half(Wsrc[(size_t)grow * DD + c]);
    }
    if (role == 0) {
        for (int idx = tid; idx < 192 * EMBD; idx += bd) {
            int r = idx / EMBD, c = idx % EMBD;
            int grow = (r >> 6) * DD + ci * 64 + (r & 63);
            wih0[idx] = eWih0[grow * EMBD + c];
        }
        if (tid < 192) {
            int grow = (tid >> 6) * DD + ci * 64 + (tid & 63);
            bA[tid] = ebih0[grow];
            bB[tid] = ebhh0[grow];
        }
        if (tid < EMBD) xs[tid] = emb[input_mol[0] * EMBD + tid];
    } else if (role == 1) {
        if (tid < 192) bA[tid] = ebih1[ci * 192 + tid];
    } else {
        if (tid < 192) {
            int grow = (tid >> 6) * DD + ci * 64 + (tid & 63);
            bB[tid] = ebhh1[grow];
        }
    }
    for (int i = tid; i < DD; i += bd) hA[i] = 0.f;
    if (tid < 256) hh2[tid] = __floats2half2_rn(0.f, 0.f);
    __syncthreads();

    if (role == 0) {
        // ---- layer-0 recurrence ----
        for (int t = 0; t < SQ; t++) {
            if (tid < 384) {
                int r = tid >> 1, p = tid & 1;
                float part = mvrow_h((const uint4*)WtH + r, h4, p);
                part += __shfl_xor_sync(0xffffffffu, part, 1);
                if (!p) {
                    dots[r] = part + bB[r];
                    float gi = bA[r];
                    #pragma unroll
                    for (int c = 0; c < EMBD; c++) gi += wih0[r * EMBD + c] * xs[c];
                    g192[r] = gi;
                }
            }
            __syncthreads();
            float xn = 0.f;
            if (t + 1 < SQ && tid < EMBD) xn = emb[input_mol[t + 1] * EMBD + tid];
            if (tid < 64) {
                float r = sigm(g192[tid] + dots[tid]);
                float z = sigm(g192[64 + tid] + dots[64 + tid]);
                float n = tanhf(g192[128 + tid] + r * dots[128 + tid]);
                float h = (1.f - z) * n + z * hA[ci * 64 + tid];
                __stcg(&g_h0seq[(size_t)t * DD + ci * 64 + tid], h);
            }
            __syncthreads();
            if (tid == 0) p_arrive(&g_cnt0.v);       // release to stage 1
            CLUSTER_SYNC();
            if (tid < 128) {
                float4 v = __ldcg((const float4*)(g_h0seq + (size_t)t * DD) + tid);
                ((float4*)hA)[tid] = v;
                hh2[tid * 2]     = __floats2half2_rn(v.x, v.y);
                hh2[tid * 2 + 1] = __floats2half2_rn(v.z, v.w);
            }
            if (tid < EMBD) xs[tid] = xn;
            __syncthreads();
        }
    } else if (role == 1) {
        // ---- gi1_t = Wih1 * h0_t + bih1 (no recurrence) ----
        for (int t = 0; t < SQ; t++) {
            if (tid == 384) p_wait_ge(&g_cnt0.v, 8u * (unsigned)(t + 1));
            __syncthreads();
            if (tid < 128) {
                float4 v = __ldcg((const float4*)(g_h0seq + (size_t)t * DD) + tid);
                hh2[tid * 2]     = __floats2half2_rn(v.x, v.y);
                hh2[tid * 2 + 1] = __floats2half2_rn(v.z, v.w);
            }
            __syncthreads();
            if (tid < 384) {
                int r = tid >> 1, p = tid & 1;
                float part = mvrow_h((const uint4*)WtH + r, h4, p);
                part += __shfl_xor_sync(0xffffffffu, part, 1);
                if (!p) __stcg(&g_gi1seq[(size_t)t * (3 * DD) + ci * 192 + r], part + bA[r]);
            }
            __syncthreads();
            if (tid == 0) p_arrive(&g_cnt1.v);
        }
    } else {
        // ---- layer-1 recurrence ----
        for (int t = 0; t < SQ; t++) {
            if (tid >= 384) {                         // warp 12: poll + fetch gi1
                if (tid == 384) p_wait_ge(&g_cnt1.v, 8u * (unsigned)(t + 1));
                __syncwarp(0xffffffffu);
                for (int idx = tid - 384; idx < 192; idx += 32) {
                    int grow = (idx >> 6) * DD + ci * 64 + (idx & 63);
                    g192[idx] = __ldcg(&g_gi1seq[(size_t)t * (3 * DD) + grow]);
                }
            } else {
                int r = tid >> 1, p = tid & 1;
                float part = mvrow_h((const uint4*)WtH + r, h4, p);
                part += __shfl_xor_sync(0xffffffffu, part, 1);
                if (!p) dots[r] = part + bB[r];
            }
            __syncthreads();
            if (tid < 64) {
                float r = sigm(g192[tid] + dots[tid]);
                float z = sigm(g192[64 + tid] + dots[64 + tid]);
                float n = tanhf(g192[128 + tid] + r * dots[128 + tid]);
                float h = (1.f - z) * n + z * hA[ci * 64 + tid];
                __stcg(&g_h1x[t & 1][ci * 64 + tid], h);
            }
            CLUSTER_SYNC();
            if (tid < 128) {
                float4 v = __ldcg((const float4*)(g_h1x[t & 1]) + tid);
                ((float4*)hA)[tid] = v;
                hh2[tid * 2]     = __floats2half2_rn(v.x, v.y);
                hh2[tid * 2 + 1] = __floats2half2_rn(v.z, v.w);
            }
            __syncthreads();
        }
    }
}

// ---------------- mid ----------------
__global__ void k_mid(const float* __restrict__ dWih1, const float* __restrict__ dbih1) {
    const float* dense = g_h1x[1];
    int w = threadIdx.x >> 5, lane = threadIdx.x & 31;
    for (int g = w; g < GHX; g += 16) {
        const float* row = dWih1 + (size_t)g * XIN;
        float acc = 0.f;
        for (int c = lane; c < DD; c += 32) acc += row[c] * dense[c];
        #pragma unroll
        for (int o = 16; o; o >>= 1) acc += __shfl_xor_sync(0xffffffffu, acc, o);
        if (lane == 0) g_dense_gi[g] = dbih1[g] + acc;
    }
}

// ---------------- decoder: 1 hop/step, hoisted gh matvecs ----------------
__global__ void __launch_bounds__(512, 1) k_decoder(
    const float* __restrict__ dWih1,
    const float* __restrict__ dWhh1, const float* __restrict__ dWih2,
    const float* __restrict__ dWhh2,
    const float* __restrict__ dbhh1, const float* __restrict__ dbih2,
    const float* __restrict__ dbhh2,
    const float* __restrict__ W2, const float* __restrict__ b2,
    float* __restrict__ out)
{
    extern __shared__ unsigned char smraw[];
    __half* WfbH = (__half*)smraw;                 // [151][264] (row 150 = ones -> Z)
    __half* W2tH = WfbH + NFB * WFBP;              // [50][256]
    __half* esh  = W2tH + HH * VPBP;               // [256]
    float*  fp   = (float*)(esh + VPBP);
    float*  tW1  = fp;  fp += HH * GHXP;
    float*  tW2i = fp;  fp += HH * GHXP;
    float*  tW2h = fp;  fp += HH * GHXP;
    float*  sgi  = fp;  fp += GHX;
    float*  sb1  = fp;  fp += GHX;
    float*  sb2i = fp;  fp += GHX;
    float*  sb2h = fp;  fp += GHX;
    float*  gh1s = fp;  fp += GHX;
    float*  gh2s = fp;  fp += GHX;
    float*  gi2s = fp;  fp += GHX;
    float*  ugf  = fp;  fp += 152;
    float*  h1s  = fp;  fp += 64;
    float*  h2os = fp;  fp += 64;

    const int b = blockIdx.x, tid = threadIdx.x;
    const int j0 = b * VPB;
    const int w = tid >> 5;
    const int lane = tid & 31;
    const int jcol = tid >> 1, hpar = tid & 1;
    const int sub = lane >> 3, kk = lane & 7;

    for (int idx = tid; idx < NFB * WFBP; idx += 512) {
        int r = idx / WFBP, c = idx % WFBP;
        float v = 0.f;
        if (c < VPB) v = (r < GHX) ? dWih1[(size_t)r * XIN + DD + j0 + c] : 1.f;
        WfbH[idx] = __float2half(v);
    }
    for (int idx = tid; idx < HH * VPBP; idx += 512) {
        int c = idx >> 8, j = idx & 255;
        W2tH[idx] = __float2half((j < VPB) ? W2[(size_t)(j0 + j) * HH + c] : 0.f);
    }
    for (int idx = tid; idx < HH * GHX; idx += 512) {
        int g = idx / HH, c = idx % HH;
        tW1 [c * GHXP + g] = dWhh1[idx];
        tW2i[c * GHXP + g] = dWih2[idx];
        tW2h[c * GHXP + g] = dWhh2[idx];
    }
    if (tid < GHX) {
        sgi[tid] = g_dense_gi[tid];
        sb1[tid] = dbhh1[tid]; sb2i[tid] = dbih2[tid]; sb2h[tid] = dbhh2[tid];
    }
    if (tid < 64) { h1s[tid] = 0.f; h2os[tid] = 0.f; }
    if (tid >= VPB && tid < VPBP) esh[tid] = __float2half(0.f);
    const float b2r = (!hpar && jcol < VPB) ? b2[j0 + jcol] : 0.f;
    __syncthreads();

    float eprev = 0.f;
    const float* accR = g_acc;

    for (int t = 0; t < SQ; t++) {
        // hoisted gh matvecs (prev-step state) + concurrent polling (warp 13)
        if (tid < GHX) {
            float a = sb1[tid];
            #pragma unroll
            for (int c = 0; c < HH; c++) a += tW1[c * GHXP + tid] * h1s[c];
            gh1s[tid] = a;
        } else if (tid >= 256 && tid < 256 + GHX) {
            int r = tid - 256;
            float a = sb2h[r];
            #pragma unroll
            for (int c = 0; c < HH; c++) a += tW2h[c * GHXP + r] * h2os[c];
            gh2s[r] = a;
        } else if (tid >= 416 && tid < 424 && t > 0) {
            p_wait_ge(&g_cntD8[tid - 416].v, 16u * (unsigned)t);
        }
        __syncthreads();
        if (tid < NFB) ugf[tid] = __ldcg(accR + tid * 32);
        __syncthreads();
        const float rz = 1.f / ugf[GHX];

        // layer-1 update (gi is elementwise)
        if (tid < HH) {
            float gr = sgi[tid]          + ugf[tid] * rz          + gh1s[tid];
            float gz = sgi[HH + tid]     + ugf[HH + tid] * rz     + gh1s[HH + tid];
            float gn = sgi[2 * HH + tid] + ugf[2 * HH + tid] * rz;
            float r = sigm(gr), z = sigm(gz);
            float n = tanhf(gn + r * gh1s[2 * HH + tid]);
            h1s[tid] = (1.f - z) * n + z * h1s[tid];
        }
        __syncthreads();
        if (tid < GHX) {
            float a = sb2i[tid];
            #pragma unroll
            for (int c = 0; c < HH; c++) a += tW2i[c * GHXP + tid] * h1s[c];
            gi2s[tid] = a;
        }
        __syncthreads();
        if (tid < HH) {
            float r = sigm(gi2s[tid] + gh2s[tid]);
            float z = sigm(gi2s[HH + tid] + gh2s[HH + tid]);
            float n = tanhf(gi2s[2 * HH + tid] + r * gh2s[2 * HH + tid]);
            h2os[tid] = (1.f - z) * n + z * h2os[tid];
        }
        __syncthreads();

        // logits (pair-split) + exp
        float acc = b2r;
        {
            const int c0 = hpar * 25;
            #pragma unroll
            for (int c = 0; c < 25; c++)
                acc += h2os[c0 + c] * __half2float(W2tH[(c0 + c) * VPBP + jcol]);
        }
        acc += __shfl_xor_sync(0xffffffffu, acc, 1);
        float e = __expf(acc);
        if (!hpar && jcol < VPB) esh[jcol] = __float2half(e);
        __syncthreads();

        // fb matvec incl Z row (151 rows), partials -> per-step lines
        float* accW = g_acc + (size_t)(t + 1) * NFB * 32;
        const uint4* es4 = (const uint4*)esh;
        uint4 ev0 = es4[kk], ev1 = es4[kk + 8], ev2 = es4[kk + 16], ev3 = es4[kk + 24];
        #pragma unroll
        for (int p = 0; p < 3; p++) {
            int row = p * 64 + w * 4 + sub;
            int rowc = (row < NFB) ? row : (NFB - 1);
            const uint4* wr = (const uint4*)(WfbH + rowc * WFBP);
            float a = dot8h(wr[kk], ev0) + dot8h(wr[kk + 8], ev1)
                    + dot8h(wr[kk + 16], ev2) + dot8h(wr[kk + 24], ev3);
            a += __shfl_xor_sync(0xffffffffu, a, 1);
            a += __shfl_xor_sync(0xffffffffu, a, 2);
            a += __shfl_xor_sync(0xffffffffu, a, 4);
            if (kk == 0 && row < NFB) atomicAdd(accW + row * 32, a);
        }
        __syncthreads();
        if (tid == 0) p_arrive(&g_cntD8[b & 7].v);

        // previous step's normalized output (off critical path)
        if (t > 0 && !hpar && jcol < VPB)
            __stcs(&out[(size_t)(t - 1) * VV + j0 + jcol], eprev * rz);
        eprev = e;
        accR += NFB * 32;
    }

    // epilogue
    if (tid < 8) p_wait_ge(&g_cntD8[tid].v, 16u * (unsigned)SQ);
    __syncthreads();
    if (tid == 0) ugf[0] = 1.f / __ldcg(g_acc + (size_t)SQ * NFB * 32 + GHX * 32);
    __syncthreads();
    if (!hpar && jcol < VPB)
        __stcs(&out[(size_t)(SQ - 1) * VV + j0 + jcol], eprev * ugf[0]);
}

// ---------------- launcher ----------------
extern "C" void kernel_launch(void* const* d_in, const int* in_sizes, int n_in,
                              void* d_out, int out_size) {
    const int*   input_mol = (const int*)  d_in[0];
    const float* emb   = (const float*)d_in[1];
    const float* eWih0 = (const float*)d_in[2];
    const float* eWhh0 = (const float*)d_in[3];
    const float* ebih0 = (const float*)d_in[4];
    const float* ebhh0 = (const float*)d_in[5];
    const float* eWih1 = (const float*)d_in[6];
    const float* eWhh1 = (const float*)d_in[7];
    const float* ebih1 = (const float*)d_in[8];
    const float* ebhh1 = (const float*)d_in[9];
    const float* dWih1 = (const float*)d_in[10];
    const float* dWhh1 = (const float*)d_in[11];
    const float* dbih1 = (const float*)d_in[12];
    const float* dbhh1 = (const float*)d_in[13];
    const float* dWih2 = (const float*)d_in[14];
    const float* dWhh2 = (const float*)d_in[15];
    const float* dbih2 = (const float*)d_in[16];
    const float* dbhh2 = (const float*)d_in[17];
    const float* W2    = (const float*)d_in[18];
    const float* b2    = (const float*)d_in[19];
    float* out = (float*)d_out;

    const size_t esmem = (size_t)192 * 512 * 2
                       + (size_t)(DD + 192 + 192 + 192 * EMBD + 192 + 192 + 16) * sizeof(float)
                       + 256 * sizeof(__half2);
    const size_t dsmem = (size_t)(NFB * WFBP + HH * VPBP + VPBP) * sizeof(__half)
                       + (size_t)(3 * HH * GHXP + 7 * GHX + 152 + 2 * 64) * sizeof(float);

    cudaFuncSetAttribute(k_encoder, cudaFuncAttributeMaxDynamicSharedMemorySize, (int)esmem);
    cudaFuncSetAttribute(k_decoder, cudaFuncAttributeMaxDynamicSharedMemorySize, (int)dsmem);

    k_init<<<((SQ + 1) * NFB + 255) / 256, 256>>>();
    k_encoder<<<24, 416, esmem>>>(input_mol, emb, eWih0, eWhh0, ebih0, ebhh0,
                                  eWih1, eWhh1, ebih1, ebhh1);
    k_mid<<<1, 512>>>(dWih1, dbih1);
    k_decoder<<<NBD, 512, dsmem>>>(dWih1, dWhh1, dWih2, dWhh2,
                                   dbhh1, dbih2, dbhh2, W2, b2, out);
}

// round 7
// speedup vs baseline: 2.5683x; 1.1256x over previous
#include <cuda_runtime.h>
#include <cuda_fp16.h>
#include <math.h>

#define SQ   4096
#define DD   512
#define VV   32000
#define HH   50
#define GHX  150
#define GHXP 160
#define EMBD 10
#define XIN  (DD + VV)

#define NBD  128
#define VPB  250
#define VPBP 256
#define WFBP 264
#define NFB  151      // 150 fb rows + Z row

// ---------------- device scratch ----------------
__device__ float g_h0seq[(size_t)SQ * DD];
__device__ float g_gi1seq[(size_t)SQ * 3 * DD];
__device__ __align__(16) float g_h1x[2][DD];
__device__ float g_dense_gi[GHX];
// 3 rotating accumulator buffers; each row = one 128B line with 8 replica slots
__device__ __align__(16) float g_acc3[3][NFB * 32];

struct __align__(128) PadCtr { unsigned int v; unsigned int pad[31]; };
__device__ PadCtr g_cnt0, g_cnt1, g_cntD8[8];

__device__ __forceinline__ float sigm(float x) { return 1.f / (1.f + __expf(-x)); }

__device__ __forceinline__ void p_arrive(unsigned int* c) {
    asm volatile("red.release.gpu.add.u32 [%0], %1;" :: "l"(c), "r"(1u) : "memory");
}
__device__ __forceinline__ void p_wait_ge(unsigned int* p, unsigned int tgt) {
    unsigned int v;
    do { asm volatile("ld.acquire.gpu.u32 %0, [%1];" : "=r"(v) : "l"(p) : "memory"); }
    while ((int)(v - tgt) < 0);
}
#define CLUSTER_SYNC() do { \
    asm volatile("barrier.cluster.arrive.aligned;" ::: "memory"); \
    asm volatile("barrier.cluster.wait.aligned;" ::: "memory"); } while (0)

__device__ __forceinline__ float dot8h(uint4 a, uint4 b) {
    const __half2* pa = (const __half2*)&a;
    const __half2* pb = (const __half2*)&b;
    float acc = 0.f;
    #pragma unroll
    for (int i = 0; i < 4; i++) {
        float2 x = __half22float2(pa[i]);
        float2 y = __half22float2(pb[i]);
        acc += x.x * y.x + x.y * y.y;
    }
    return acc;
}

// conflict-free half matvec partial: warp handles rows W16..W16+15, lane (h,i)
// accumulates cols [h*256, h*256+256) of row W16+i. Chunk (cb,r) at uint4 index
// cb*192 + r; 16 lanes read 256 contiguous bytes -> zero bank conflicts.
__device__ __forceinline__ float mv_cf(const uint4* WtH4, const uint4* h4,
                                       int r, int hh) {
    const uint4* wp = WtH4 + (hh << 5) * 192 + r;
    float acc = 0.f;
    #pragma unroll
    for (int jo = 0; jo < 8; jo++) {
        __half2 ha = __floats2half2_rn(0.f, 0.f);
        #pragma unroll
        for (int ji = 0; ji < 4; ji++) {
            int j = (jo << 2) + ji;
            uint4 wv = wp[j * 192];
            uint4 hv = h4[(hh << 5) + j];
            const __half2* a2 = (const __half2*)&wv;
            const __half2* b2 = (const __half2*)&hv;
            ha = __hfma2(a2[0], b2[0], ha);
            ha = __hfma2(a2[1], b2[1], ha);
            ha = __hfma2(a2[2], b2[2], ha);
            ha = __hfma2(a2[3], b2[3], ha);
        }
        float2 f = __half22float2(ha);
        acc += f.x + f.y;
    }
    acc += __shfl_xor_sync(0xffffffffu, acc, 16);
    return acc;
}

// ---------------- init ----------------
__global__ void k_init() {
    int t = blockIdx.x * blockDim.x + threadIdx.x;
    if (t == 0) { g_cnt0.v = 0u; g_cnt1.v = 0u; }
    if (t < 8)  g_cntD8[t].v = 0u;
    if (t < 3 * NFB * 32)
        ((float*)g_acc3)[t] = (t == GHX * 32) ? 1.f : 0.f;  // buf0: ugfb=0, Z=1
}

// ---------------- encoder: 3 pipelined clusters of 8 CTAs ----------------
__global__ void __launch_bounds__(416, 1) __cluster_dims__(8, 1, 1)
k_encoder(
    const int*   __restrict__ input_mol, const float* __restrict__ emb,
    const float* __restrict__ eWih0, const float* __restrict__ eWhh0,
    const float* __restrict__ ebih0, const float* __restrict__ ebhh0,
    const float* __restrict__ eWih1, const float* __restrict__ eWhh1,
    const float* __restrict__ ebih1, const float* __restrict__ ebhh1)
{
    extern __shared__ unsigned char smraw[];
    __half*  WtH  = (__half*)smraw;                       // 192*512 chunked
    float*   fp   = (float*)(smraw + 192 * 512 * 2);
    float*   hA   = fp;  fp += DD;
    float*   dots = fp;  fp += 192;
    float*   g192 = fp;  fp += 192;
    float*   wih0 = fp;  fp += 192 * EMBD;
    float*   bA   = fp;  fp += 192;
    float*   bB   = fp;  fp += 192;
    float*   xs   = fp;  fp += 16;
    __half2* hh2  = (__half2*)fp;                         // 256 half2

    const int tid  = threadIdx.x;
    const int role = blockIdx.x >> 3;
    const int ci   = blockIdx.x & 7;
    const int bd   = blockDim.x;
    const uint4* h4 = (const uint4*)hh2;
    const uint4* W4 = (const uint4*)WtH;

    const float* Wsrc = (role == 0) ? eWhh0 : (role == 1) ? eWih1 : eWhh1;
    for (int idx = tid; idx < 192 * 512; idx += bd) {
        int r = idx >> 9, c = idx & 511;
        int grow = (role == 1) ? (ci * 192 + r) : ((r >> 6) * DD + ci * 64 + (r & 63));
        WtH[((c >> 3) * 192 + r) * 8 + (c & 7)] = __float2half(Wsrc[(size_t)grow * DD + c]);
    }
    if (role == 0) {
        for (int idx = tid; idx < 192 * EMBD; idx += bd) {
            int r = idx / EMBD, c = idx % EMBD;
            int grow = (r >> 6) * DD + ci * 64 + (r & 63);
            wih0[idx] = eWih0[grow * EMBD + c];
        }
        if (tid < 192) {
            int grow = (tid >> 6) * DD + ci * 64 + (tid & 63);
            bA[tid] = ebih0[grow];
            bB[tid] = ebhh0[grow];
        }
        if (tid < EMBD) xs[tid] = emb[input_mol[0] * EMBD + tid];
    } else if (role == 1) {
        if (tid < 192) bA[tid] = ebih1[ci * 192 + tid];
    } else {
        if (tid < 192) {
            int grow = (tid >> 6) * DD + ci * 64 + (tid & 63);
            bB[tid] = ebhh1[grow];
        }
    }
    for (int i = tid; i < DD; i += bd) hA[i] = 0.f;
    if (tid < 256) hh2[tid] = __floats2half2_rn(0.f, 0.f);
    __syncthreads();

    if (role == 0) {
        for (int t = 0; t < SQ; t++) {
            if (tid < 384) {
                const int l = tid & 31, ii = l & 15, hh = l >> 4;
                const int r = ((tid >> 5) << 4) + ii;
                float acc = mv_cf(W4, h4, r, hh);
                if (hh == 0) dots[r] = acc + bB[r];
                else {
                    float gi = bA[r];
                    #pragma unroll
                    for (int c = 0; c < EMBD; c++) gi += wih0[r * EMBD + c] * xs[c];
                    g192[r] = gi;
                }
            }
            __syncthreads();
            float xn = 0.f;
            if (t + 1 < SQ && tid < EMBD) xn = emb[input_mol[t + 1] * EMBD + tid];
            if (tid < 64) {
                float r = sigm(g192[tid] + dots[tid]);
                float z = sigm(g192[64 + tid] + dots[64 + tid]);
                float n = tanhf(g192[128 + tid] + r * dots[128 + tid]);
                float h = (1.f - z) * n + z * hA[ci * 64 + tid];
                __stcg(&g_h0seq[(size_t)t * DD + ci * 64 + tid], h);
            }
            __syncthreads();
            if (tid == 0) p_arrive(&g_cnt0.v);
            CLUSTER_SYNC();
            if (tid < 128) {
                float4 v = __ldcg((const float4*)(g_h0seq + (size_t)t * DD) + tid);
                ((float4*)hA)[tid] = v;
                hh2[tid * 2]     = __floats2half2_rn(v.x, v.y);
                hh2[tid * 2 + 1] = __floats2half2_rn(v.z, v.w);
            }
            if (tid < EMBD) xs[tid] = xn;
            __syncthreads();
        }
    } else if (role == 1) {
        for (int t = 0; t < SQ; t++) {
            if (tid == 384) p_wait_ge(&g_cnt0.v, 8u * (unsigned)(t + 1));
            __syncthreads();
            if (tid < 128) {
                float4 v = __ldcg((const float4*)(g_h0seq + (size_t)t * DD) + tid);
                hh2[tid * 2]     = __floats2half2_rn(v.x, v.y);
                hh2[tid * 2 + 1] = __floats2half2_rn(v.z, v.w);
            }
            __syncthreads();
            if (tid < 384) {
                const int l = tid & 31, ii = l & 15, hh = l >> 4;
                const int r = ((tid >> 5) << 4) + ii;
                float acc = mv_cf(W4, h4, r, hh);
                if (hh == 0)
                    __stcg(&g_gi1seq[(size_t)t * (3 * DD) + ci * 192 + r], acc + bA[r]);
            }
            __syncthreads();
            if (tid == 0) p_arrive(&g_cnt1.v);
        }
    } else {
        for (int t = 0; t < SQ; t++) {
            if (tid >= 384) {
                if (tid == 384) p_wait_ge(&g_cnt1.v, 8u * (unsigned)(t + 1));
                __syncwarp(0xffffffffu);
                for (int idx = tid - 384; idx < 192; idx += 32) {
                    int grow = (idx >> 6) * DD + ci * 64 + (idx & 63);
                    g192[idx] = __ldcg(&g_gi1seq[(size_t)t * (3 * DD) + grow]);
                }
            } else {
                const int l = tid & 31, ii = l & 15, hh = l >> 4;
                const int r = ((tid >> 5) << 4) + ii;
                float acc = mv_cf(W4, h4, r, hh);
                if (hh == 0) dots[r] = acc + bB[r];
            }
            __syncthreads();
            if (tid < 64) {
                float r = sigm(g192[tid] + dots[tid]);
                float z = sigm(g192[64 + tid] + dots[64 + tid]);
                float n = tanhf(g192[128 + tid] + r * dots[128 + tid]);
                float h = (1.f - z) * n + z * hA[ci * 64 + tid];
                __stcg(&g_h1x[t & 1][ci * 64 + tid], h);
            }
            CLUSTER_SYNC();
            if (tid < 128) {
                float4 v = __ldcg((const float4*)(g_h1x[t & 1]) + tid);
                ((float4*)hA)[tid] = v;
                hh2[tid * 2]     = __floats2half2_rn(v.x, v.y);
                hh2[tid * 2 + 1] = __floats2half2_rn(v.z, v.w);
            }
            __syncthreads();
        }
    }
}

// ---------------- mid ----------------
__global__ void k_mid(const float* __restrict__ dWih1, const float* __restrict__ dbih1) {
    const float* dense = g_h1x[1];
    int w = threadIdx.x >> 5, lane = threadIdx.x & 31;
    for (int g = w; g < GHX; g += 16) {
        const float* row = dWih1 + (size_t)g * XIN;
        float acc = 0.f;
        for (int c = lane; c < DD; c += 32) acc += row[c] * dense[c];
        #pragma unroll
        for (int o = 16; o; o >>= 1) acc += __shfl_xor_sync(0xffffffffu, acc, o);
        if (lane == 0) g_dense_gi[g] = dbih1[g] + acc;
    }
}

// ---------------- decoder: 1 hop/step, 8-replica accumulators ----------------
__global__ void __launch_bounds__(512, 1) k_decoder(
    const float* __restrict__ dWih1,
    const float* __restrict__ dWhh1, const float* __restrict__ dWih2,
    const float* __restrict__ dWhh2,
    const float* __restrict__ dbhh1, const float* __restrict__ dbih2,
    const float* __restrict__ dbhh2,
    const float* __restrict__ W2, const float* __restrict__ b2,
    float* __restrict__ out)
{
    extern __shared__ unsigned char smraw[];
    __half* WfbH = (__half*)smraw;                 // [151][264] (row 150 = ones)
    __half* W2tH = WfbH + NFB * WFBP;              // [50][256]
    __half* esh  = W2tH + HH * VPBP;               // [256]
    float*  fp   = (float*)(esh + VPBP);
    float*  tW1  = fp;  fp += HH * GHXP;
    float*  tW2i = fp;  fp += HH * GHXP;
    float*  tW2h = fp;  fp += HH * GHXP;
    float*  sgi  = fp;  fp += GHX;
    float*  sb1  = fp;  fp += GHX;
    float*  sb2i = fp;  fp += GHX;
    float*  sb2h = fp;  fp += GHX;
    float*  gh1s = fp;  fp += GHX;
    float*  gh2s = fp;  fp += GHX;
    float*  gi2s = fp;  fp += GHX;
    float*  ugf  = fp;  fp += 152;
    float*  h1s  = fp;  fp += 64;
    float*  h2os = fp;  fp += 64;

    const int b = blockIdx.x, tid = threadIdx.x;
    const int j0 = b * VPB;
    const int slot = b & 7;
    const int w = tid >> 5;
    const int lane = tid & 31;
    const int jcol = tid >> 1, hpar = tid & 1;
    const int sub = lane >> 3, kk = lane & 7;

    for (int idx = tid; idx < NFB * WFBP; idx += 512) {
        int r = idx / WFBP, c = idx % WFBP;
        float v = 0.f;
        if (c < VPB) v = (r < GHX) ? dWih1[(size_t)r * XIN + DD + j0 + c] : 1.f;
        WfbH[idx] = __float2half(v);
    }
    for (int idx = tid; idx < HH * VPBP; idx += 512) {
        int c = idx >> 8, j = idx & 255;
        W2tH[idx] = __float2half((j < VPB) ? W2[(size_t)(j0 + j) * HH + c] : 0.f);
    }
    for (int idx = tid; idx < HH * GHX; idx += 512) {
        int g = idx / HH, c = idx % HH;
        tW1 [c * GHXP + g] = dWhh1[idx];
        tW2i[c * GHXP + g] = dWih2[idx];
        tW2h[c * GHXP + g] = dWhh2[idx];
    }
    if (tid < GHX) {
        sgi[tid] = g_dense_gi[tid];
        sb1[tid] = dbhh1[tid]; sb2i[tid] = dbih2[tid]; sb2h[tid] = dbhh2[tid];
    }
    if (tid < 64) { h1s[tid] = 0.f; h2os[tid] = 0.f; }
    if (tid >= VPB && tid < VPBP) esh[tid] = __float2half(0.f);
    const float b2r = (!hpar && jcol < VPB) ? b2[j0 + jcol] : 0.f;
    __syncthreads();

    float eprev = 0.f;

    for (int t = 0; t < SQ; t++) {
        // hoisted gh matvecs (prev state) concurrent with counter polling
        if (tid < GHX) {
            float a = sb1[tid];
            #pragma unroll
            for (int c = 0; c < HH; c++) a += tW1[c * GHXP + tid] * h1s[c];
            gh1s[tid] = a;
        } else if (tid >= 256 && tid < 256 + GHX) {
            int r = tid - 256;
            float a = sb2h[r];
            #pragma unroll
            for (int c = 0; c < HH; c++) a += tW2h[c * GHXP + r] * h2os[c];
            gh2s[r] = a;
        } else if (tid >= 416 && tid < 424 && t > 0) {
            p_wait_ge(&g_cntD8[tid - 416].v, 16u * (unsigned)t);
        }
        __syncthreads();
        // zero next-next buffer slot; read current (sum 8 replicas in one line)
        {
            float* bufR = g_acc3[t % 3];
            float* bufZ = g_acc3[(t + 2) % 3];
            if (tid < NFB) {
                __stcg(&bufZ[tid * 32 + slot], 0.f);
                float4 a = __ldcg((const float4*)(bufR + tid * 32));
                float4 c = __ldcg((const float4*)(bufR + tid * 32) + 1);
                ugf[tid] = ((a.x + a.y) + (a.z + a.w)) + ((c.x + c.y) + (c.z + c.w));
            }
        }
        __syncthreads();
        const float rz = 1.f / ugf[GHX];

        if (tid < HH) {
            float gr = sgi[tid]          + ugf[tid] * rz          + gh1s[tid];
            float gz = sgi[HH + tid]     + ugf[HH + tid] * rz     + gh1s[HH + tid];
            float gn = sgi[2 * HH + tid] + ugf[2 * HH + tid] * rz;
            float r = sigm(gr), z = sigm(gz);
            float n = tanhf(gn + r * gh1s[2 * HH + tid]);
            h1s[tid] = (1.f - z) * n + z * h1s[tid];
        }
        __syncthreads();
        if (tid < GHX) {
            float a = sb2i[tid];
            #pragma unroll
            for (int c = 0; c < HH; c++) a += tW2i[c * GHXP + tid] * h1s[c];
            gi2s[tid] = a;
        }
        __syncthreads();
        if (tid < HH) {
            float r = sigm(gi2s[tid] + gh2s[tid]);
            float z = sigm(gi2s[HH + tid] + gh2s[HH + tid]);
            float n = tanhf(gi2s[2 * HH + tid] + r * gh2s[2 * HH + tid]);
            h2os[tid] = (1.f - z) * n + z * h2os[tid];
        }
        __syncthreads();

        float acc = b2r;
        {
            const int c0 = hpar * 25;
            #pragma unroll
            for (int c = 0; c < 25; c++)
                acc += h2os[c0 + c] * __half2float(W2tH[(c0 + c) * VPBP + jcol]);
        }
        acc += __shfl_xor_sync(0xffffffffu, acc, 1);
        float e = __expf(acc);
        if (!hpar && jcol < VPB) esh[jcol] = __float2half(e);
        __syncthreads();

        float* accW = g_acc3[(t + 1) % 3];
        const uint4* es4 = (const uint4*)esh;
        uint4 ev0 = es4[kk], ev1 = es4[kk + 8], ev2 = es4[kk + 16], ev3 = es4[kk + 24];
        #pragma unroll
        for (int p = 0; p < 3; p++) {
            int row = p * 64 + w * 4 + sub;
            int rowc = (row < NFB) ? row : (NFB - 1);
            const uint4* wr = (const uint4*)(WfbH + rowc * WFBP);
            float a = dot8h(wr[kk], ev0) + dot8h(wr[kk + 8], ev1)
                    + dot8h(wr[kk + 16], ev2) + dot8h(wr[kk + 24], ev3);
            a += __shfl_xor_sync(0xffffffffu, a, 1);
            a += __shfl_xor_sync(0xffffffffu, a, 2);
            a += __shfl_xor_sync(0xffffffffu, a, 4);
            if (kk == 0 && row < NFB) atomicAdd(&accW[row * 32 + slot], a);
        }
        __syncthreads();
        if (tid == 0) p_arrive(&g_cntD8[b & 7].v);

        if (t > 0 && !hpar && jcol < VPB)
            __stcs(&out[(size_t)(t - 1) * VV + j0 + jcol], eprev * rz);
        eprev = e;
    }

    // epilogue
    if (tid < 8) p_wait_ge(&g_cntD8[tid].v, 16u * (unsigned)SQ);
    __syncthreads();
    if (tid == 0) {
        const float* zr = g_acc3[SQ % 3] + GHX * 32;
        float z = 0.f;
        #pragma unroll
        for (int i = 0; i < 8; i++) z += __ldcg(zr + i);
        ugf[0] = 1.f / z;
    }
    __syncthreads();
    if (!hpar && jcol < VPB)
        __stcs(&out[(size_t)(SQ - 1) * VV + j0 + jcol], eprev * ugf[0]);
}

// ---------------- launcher ----------------
extern "C" void kernel_launch(void* const* d_in, const int* in_sizes, int n_in,
                              void* d_out, int out_size) {
    const int*   input_mol = (const int*)  d_in[0];
    const float* emb   = (const float*)d_in[1];
    const float* eWih0 = (const float*)d_in[2];
    const float* eWhh0 = (const float*)d_in[3];
    const float* ebih0 = (const float*)d_in[4];
    const float* ebhh0 = (const float*)d_in[5];
    const float* eWih1 = (const float*)d_in[6];
    const float* eWhh1 = (const float*)d_in[7];
    const float* ebih1 = (const float*)d_in[8];
    const float* ebhh1 = (const float*)d_in[9];
    const float* dWih1 = (const float*)d_in[10];
    const float* dWhh1 = (const float*)d_in[11];
    const float* dbih1 = (const float*)d_in[12];
    const float* dbhh1 = (const float*)d_in[13];
    const float* dWih2 = (const float*)d_in[14];
    const float* dWhh2 = (const float*)d_in[15];
    const float* dbih2 = (const float*)d_in[16];
    const float* dbhh2 = (const float*)d_in[17];
    const float* W2    = (const float*)d_in[18];
    const float* b2    = (const float*)d_in[19];
    float* out = (float*)d_out;

    const size_t esmem = (size_t)192 * 512 * 2
                       + (size_t)(DD + 192 + 192 + 192 * EMBD + 192 + 192 + 16) * sizeof(float)
                       + 256 * sizeof(__half2);
    const size_t dsmem = (size_t)(NFB * WFBP + HH * VPBP + VPBP) * sizeof(__half)
                       + (size_t)(3 * HH * GHXP + 7 * GHX + 152 + 2 * 64) * sizeof(float);

    cudaFuncSetAttribute(k_encoder, cudaFuncAttributeMaxDynamicSharedMemorySize, (int)esmem);
    cudaFuncSetAttribute(k_decoder, cudaFuncAttributeMaxDynamicSharedMemorySize, (int)dsmem);

    k_init<<<(3 * NFB * 32 + 255) / 256, 256>>>();
    k_encoder<<<24, 416, esmem>>>(input_mol, emb, eWih0, eWhh0, ebih0, ebhh0,
                                  eWih1, eWhh1, ebih1, ebhh1);
    k_mid<<<1, 512>>>(dWih1, dbih1);
    k_decoder<<<NBD, 512, dsmem>>>(dWih1, dWhh1, dWih2, dWhh2,
                                   dbhh1, dbih2, dbhh2, W2, b2, out);
}